// round 2
// baseline (speedup 1.0000x reference)
#include <cuda_runtime.h>

typedef unsigned long long u64;

#define BB 2048
#define TT 4096
#define II 5
#define HH 10

// ---- packed fp32x2 helpers (Blackwell-only; ptxas won't auto-fuse) ----
__device__ __forceinline__ u64 pk2(float lo, float hi) {
    u64 r; asm("mov.b64 %0, {%1,%2};" : "=l"(r) : "f"(lo), "f"(hi)); return r;
}
__device__ __forceinline__ void upk2(u64 v, float &lo, float &hi) {
    asm("mov.b64 {%0,%1}, %2;" : "=f"(lo), "=f"(hi) : "l"(v));
}
__device__ __forceinline__ u64 fma2(u64 a, u64 b, u64 c) {
    u64 d; asm("fma.rn.f32x2 %0, %1, %2, %3;" : "=l"(d) : "l"(a), "l"(b), "l"(c)); return d;
}
__device__ __forceinline__ u64 add2(u64 a, u64 b) {
    u64 d; asm("add.rn.f32x2 %0, %1, %2;" : "=l"(d) : "l"(a), "l"(b)); return d;
}
// ---- fast-but-accurate transcendentals (EX2/RCP are ~1 ulp MUFU ops) ----
__device__ __forceinline__ float ex2f(float x) { float r; asm("ex2.approx.ftz.f32 %0, %1;" : "=f"(r) : "f"(x)); return r; }
__device__ __forceinline__ float rcpf(float x) { float r; asm("rcp.approx.ftz.f32 %0, %1;" : "=f"(r) : "f"(x)); return r; }
__device__ __forceinline__ float sigm(float x) {
    // 1/(1 + 2^(-x*log2 e))
    return rcpf(1.0f + ex2f(x * -1.4426950408889634f));
}
__device__ __forceinline__ float tanh_(float x) {
    // 2*sigmoid(2x) - 1
    return fmaf(2.0f, rcpf(1.0f + ex2f(x * -2.8853900817779268f)), -1.0f);
}

// Layout: 10 lanes per batch element (one hidden unit j per lane, all 4 gates
// for that unit). 3 elements per warp (lanes 0..29), lanes 30/31 idle-compute.
// h broadcast within the 10-lane group via __shfl_sync each step.
__global__ void __launch_bounds__(128, 1) lstm_kernel(
    const float* __restrict__ x,   const float* __restrict__ h0,
    const float* __restrict__ c0,  const float* __restrict__ Wih,
    const float* __restrict__ Whh, const float* __restrict__ bih,
    const float* __restrict__ bhh, float* __restrict__ out)
{
    const int lane  = threadIdx.x & 31;
    const int gwarp = (blockIdx.x * blockDim.x + threadIdx.x) >> 5;
    if (gwarp * 3 >= BB) return;                 // whole warp past the end

    int grp = lane / 10;                          // 0..2 valid, 3 = idle lanes
    int j   = lane - grp * 10;                    // hidden unit index
    bool valid = (grp < 3);
    int b = gwarp * 3 + (valid ? grp : 0);
    if (b >= BB) { valid = false; b = BB - 1; }
    const int base = (grp < 3 ? grp : 0) * 10;    // shfl source base lane

    // ---- per-thread packed weights: gates (i,f) and (g,o) as f32x2 ----
    u64 wx01[II], wx23[II], wh01[HH], wh23[HH];
#pragma unroll
    for (int k = 0; k < II; k++) {
        wx01[k] = pk2(Wih[(0 * HH + j) * II + k], Wih[(1 * HH + j) * II + k]);
        wx23[k] = pk2(Wih[(2 * HH + j) * II + k], Wih[(3 * HH + j) * II + k]);
    }
#pragma unroll
    for (int k = 0; k < HH; k++) {
        wh01[k] = pk2(Whh[(0 * HH + j) * HH + k], Whh[(1 * HH + j) * HH + k]);
        wh23[k] = pk2(Whh[(2 * HH + j) * HH + k], Whh[(3 * HH + j) * HH + k]);
    }
    const u64 b01 = pk2(bih[0 * HH + j] + bhh[0 * HH + j],
                        bih[1 * HH + j] + bhh[1 * HH + j]);
    const u64 b23 = pk2(bih[2 * HH + j] + bhh[2 * HH + j],
                        bih[3 * HH + j] + bhh[3 * HH + j]);

    float h = h0[b * HH + j];
    float c = c0[b * HH + j];

    const float* xp = x   + (size_t)b * TT * II;
    float*       op = out + (size_t)b * TT * HH + j;

    // x double buffers: 4 timesteps (20 floats) per buffer, loaded as 5×float4.
    // (b*T + t)*I*4B is 16B-aligned whenever t%4==0 since T*I*4 and 4*I*4=80
    // are both 16B multiples.
    float xa[20], xb[20];
#pragma unroll
    for (int q = 0; q < 5; q++) {
        float4 v = *reinterpret_cast<const float4*>(xp + 4 * q);
        xa[4 * q + 0] = v.x; xa[4 * q + 1] = v.y;
        xa[4 * q + 2] = v.z; xa[4 * q + 3] = v.w;
    }

    auto STEP = [&](float x0, float x1, float x2, float x3, float x4, int t) {
        // gather previous h across the 10-lane group
        float hk[10];
#pragma unroll
        for (int k = 0; k < 10; k++)
            hk[k] = __shfl_sync(0xffffffffu, h, base + k);

        // 4 accumulation chains (2 per gate-pair) for ILP
        u64 A1 = b01, A2 = 0ull, B1 = b23, B2 = 0ull;
        u64 xx0 = pk2(x0, x0), xx1 = pk2(x1, x1), xx2 = pk2(x2, x2),
            xx3 = pk2(x3, x3), xx4 = pk2(x4, x4);
        A1 = fma2(wx01[0], xx0, A1);  B1 = fma2(wx23[0], xx0, B1);
        A2 = fma2(wx01[1], xx1, A2);  B2 = fma2(wx23[1], xx1, B2);
        A1 = fma2(wx01[2], xx2, A1);  B1 = fma2(wx23[2], xx2, B1);
        A2 = fma2(wx01[3], xx3, A2);  B2 = fma2(wx23[3], xx3, B2);
        A1 = fma2(wx01[4], xx4, A1);  B1 = fma2(wx23[4], xx4, B1);
#pragma unroll
        for (int k = 0; k < 10; k++) {
            u64 hh = pk2(hk[k], hk[k]);
            if (k & 1) { A2 = fma2(wh01[k], hh, A2); B2 = fma2(wh23[k], hh, B2); }
            else       { A1 = fma2(wh01[k], hh, A1); B1 = fma2(wh23[k], hh, B1); }
        }
        u64 a01 = add2(A1, A2), a23 = add2(B1, B2);
        float gi, gf, gg, go;
        upk2(a01, gi, gf);
        upk2(a23, gg, go);
        float si = sigm(gi), sf = sigm(gf), sg = tanh_(gg), so = sigm(go);
        c = fmaf(sf, c, si * sg);
        h = so * tanh_(c);
        if (valid) op[(size_t)t * HH] = h;
    };

    for (int tb = 0; tb < TT; tb += 8) {
        // prefetch next 4 steps into xb while computing from xa
#pragma unroll
        for (int q = 0; q < 5; q++) {
            float4 v = *reinterpret_cast<const float4*>(xp + (tb + 4) * II + 4 * q);
            xb[4 * q + 0] = v.x; xb[4 * q + 1] = v.y;
            xb[4 * q + 2] = v.z; xb[4 * q + 3] = v.w;
        }
#pragma unroll
        for (int s = 0; s < 4; s++)
            STEP(xa[s * 5 + 0], xa[s * 5 + 1], xa[s * 5 + 2],
                 xa[s * 5 + 3], xa[s * 5 + 4], tb + s);

        if (tb + 8 < TT) {
#pragma unroll
            for (int q = 0; q < 5; q++) {
                float4 v = *reinterpret_cast<const float4*>(xp + (tb + 8) * II + 4 * q);
                xa[4 * q + 0] = v.x; xa[4 * q + 1] = v.y;
                xa[4 * q + 2] = v.z; xa[4 * q + 3] = v.w;
            }
        }
#pragma unroll
        for (int s = 0; s < 4; s++)
            STEP(xb[s * 5 + 0], xb[s * 5 + 1], xb[s * 5 + 2],
                 xb[s * 5 + 3], xb[s * 5 + 4], tb + 4 + s);
    }
}

extern "C" void kernel_launch(void* const* d_in, const int* in_sizes, int n_in,
                              void* d_out, int out_size)
{
    const float* x   = (const float*)d_in[0];
    const float* h0  = (const float*)d_in[1];
    const float* c0  = (const float*)d_in[2];
    const float* Wih = (const float*)d_in[3];
    const float* Whh = (const float*)d_in[4];
    const float* bih = (const float*)d_in[5];
    const float* bhh = (const float*)d_in[6];
    float* out = (float*)d_out;

    const int warps   = (BB + 2) / 3;                    // 683
    const int threads = 128;                             // 4 warps / CTA
    const int blocks  = (warps * 32 + threads - 1) / threads;  // 171
    lstm_kernel<<<blocks, threads>>>(x, h0, c0, Wih, Whh, bih, bhh, out);
}

// round 3
// speedup vs baseline: 1.0057x; 1.0057x over previous
#include <cuda_runtime.h>

typedef unsigned long long u64;

#define BB 2048
#define TT 4096
#define II 5
#define HH 10

// ---- packed fp32x2 helpers ----
__device__ __forceinline__ u64 pk2(float lo, float hi) {
    u64 r; asm("mov.b64 %0, {%1,%2};" : "=l"(r) : "f"(lo), "f"(hi)); return r;
}
__device__ __forceinline__ void upk2(u64 v, float &lo, float &hi) {
    asm("mov.b64 {%0,%1}, %2;" : "=f"(lo), "=f"(hi) : "l"(v));
}
__device__ __forceinline__ u64 fma2(u64 a, u64 b, u64 c) {
    u64 d; asm("fma.rn.f32x2 %0, %1, %2, %3;" : "=l"(d) : "l"(a), "l"(b), "l"(c)); return d;
}
__device__ __forceinline__ u64 mul2(u64 a, u64 b) {
    u64 d; asm("mul.rn.f32x2 %0, %1, %2;" : "=l"(d) : "l"(a), "l"(b)); return d;
}
// ---- MUFU ops (ex2/rcp are ~1 ulp) ----
__device__ __forceinline__ float ex2f(float x) { float r; asm("ex2.approx.ftz.f32 %0, %1;" : "=f"(r) : "f"(x)); return r; }
__device__ __forceinline__ float rcpf(float x) { float r; asm("rcp.approx.ftz.f32 %0, %1;" : "=f"(r) : "f"(x)); return r; }

#define S_SIG (-1.4426950408889634f)   // -log2(e): sigmoid prescale
#define S_TANH (-2.8853900817779268f)  // -2*log2(e): tanh prescale

// Layout: 10 lanes per batch element (unit j per lane, all 4 gates of that
// unit). 3 elements per warp (lanes 0..29). Gate accumulators are f32x2
// packed over k-parity (k even / k odd) so the fma2 multiplier is the PAIR
// (h_2m, h_2m+1) of two distinct shfl results -> no duplicate-operand MOVs.
// All weights/biases pre-scaled so activations need no extra multiplies.
__global__ void __launch_bounds__(128, 1) lstm_kernel(
    const float* __restrict__ x,   const float* __restrict__ h0,
    const float* __restrict__ c0,  const float* __restrict__ Wih,
    const float* __restrict__ Whh, const float* __restrict__ bih,
    const float* __restrict__ bhh, float* __restrict__ out)
{
    const int lane  = threadIdx.x & 31;
    const int gwarp = (blockIdx.x * blockDim.x + threadIdx.x) >> 5;
    if (gwarp * 3 >= BB) return;                 // whole warp past the end

    int grp = lane / 10;                          // 0..2 valid, 3 = idle lanes
    int j   = lane - grp * 10;                    // hidden unit index
    bool valid = (grp < 3);
    int b = gwarp * 3 + (valid ? grp : 0);
    if (b >= BB) { valid = false; b = BB - 1; }
    const int base = (valid ? grp : 0) * 10;      // shfl source base lane

    // ---- pre-scaled per-thread weights ----
    // gate order i,f,g,o; scale = S_TANH for g, S_SIG otherwise
    u64 wh[4][5];     // k-pairs (2m, 2m+1)
    u64 wx01[4], wx23[4];
    float wx4[4], bs[4];
#pragma unroll
    for (int g = 0; g < 4; g++) {
        const float s = (g == 2) ? S_TANH : S_SIG;
        const int row = (g * HH + j);
#pragma unroll
        for (int m = 0; m < 5; m++)
            wh[g][m] = pk2(s * Whh[row * HH + 2 * m], s * Whh[row * HH + 2 * m + 1]);
        wx01[g] = pk2(s * Wih[row * II + 0], s * Wih[row * II + 1]);
        wx23[g] = pk2(s * Wih[row * II + 2], s * Wih[row * II + 3]);
        wx4[g]  = s * Wih[row * II + 4];
        bs[g]   = s * (bih[g * HH + j] + bhh[g * HH + j]);
    }

    float h = h0[b * HH + j];
    float c = c0[b * HH + j];

    const float* xp = x   + (size_t)b * TT * II;
    float*       op = out + (size_t)b * TT * HH + j;

    // x double buffers: 4 timesteps (20 floats) each, loaded as 5 x float4.
    // (b*T + t)*I*4B is 16B-aligned whenever t%4==0.
    float xa[20], xb[20];
#pragma unroll
    for (int q = 0; q < 5; q++) {
        float4 v = *reinterpret_cast<const float4*>(xp + 4 * q);
        xa[4 * q + 0] = v.x; xa[4 * q + 1] = v.y;
        xa[4 * q + 2] = v.z; xa[4 * q + 3] = v.w;
    }

    auto STEP = [&](const float* xs, int t) {
        // x-part: packed pairs + scalar tail; independent of h (hoistable
        // above the shfl wait by the scheduler)
        u64 x01 = pk2(xs[0], xs[1]);
        u64 x23 = pk2(xs[2], xs[3]);
        const float x4 = xs[4];

        u64 acc[4];
        float tg[4];
#pragma unroll
        for (int g = 0; g < 4; g++) {
            acc[g] = fma2(wx01[g], x01, mul2(wx23[g], x23));
            tg[g]  = fmaf(wx4[g], x4, bs[g]);
        }

        // h-part: pair (h_2m, h_2m+1) from two shfls -> direct fma2 operand
#pragma unroll
        for (int m = 0; m < 5; m++) {
            float lo = __shfl_sync(0xffffffffu, h, base + 2 * m);
            float hi = __shfl_sync(0xffffffffu, h, base + 2 * m + 1);
            u64 hp = pk2(lo, hi);
#pragma unroll
            for (int g = 0; g < 4; g++)
                acc[g] = fma2(wh[g][m], hp, acc[g]);
        }

        // horizontal combine + activations (weights pre-scaled)
        float pre[4];
#pragma unroll
        for (int g = 0; g < 4; g++) {
            float lo, hi; upk2(acc[g], lo, hi);
            pre[g] = (lo + hi) + tg[g];
        }
        float si = rcpf(1.0f + ex2f(pre[0]));
        float sf = rcpf(1.0f + ex2f(pre[1]));
        float gg = fmaf(2.0f, rcpf(1.0f + ex2f(pre[2])), -1.0f);
        float so = rcpf(1.0f + ex2f(pre[3]));
        c = fmaf(sf, c, si * gg);
        float tc = fmaf(2.0f, rcpf(1.0f + ex2f(S_TANH * c)), -1.0f);
        h = so * tc;
        if (valid) op[(size_t)t * HH] = h;
    };

    for (int tb = 0; tb < TT; tb += 8) {
        // prefetch next 4 steps into xb while computing from xa
#pragma unroll
        for (int q = 0; q < 5; q++) {
            float4 v = *reinterpret_cast<const float4*>(xp + (tb + 4) * II + 4 * q);
            xb[4 * q + 0] = v.x; xb[4 * q + 1] = v.y;
            xb[4 * q + 2] = v.z; xb[4 * q + 3] = v.w;
        }
#pragma unroll
        for (int s = 0; s < 4; s++)
            STEP(&xa[s * 5], tb + s);

        if (tb + 8 < TT) {
#pragma unroll
            for (int q = 0; q < 5; q++) {
                float4 v = *reinterpret_cast<const float4*>(xp + (tb + 8) * II + 4 * q);
                xa[4 * q + 0] = v.x; xa[4 * q + 1] = v.y;
                xa[4 * q + 2] = v.z; xa[4 * q + 3] = v.w;
            }
        }
#pragma unroll
        for (int s = 0; s < 4; s++)
            STEP(&xb[s * 5], tb + 4 + s);
    }
}

extern "C" void kernel_launch(void* const* d_in, const int* in_sizes, int n_in,
                              void* d_out, int out_size)
{
    const float* x   = (const float*)d_in[0];
    const float* h0  = (const float*)d_in[1];
    const float* c0  = (const float*)d_in[2];
    const float* Wih = (const float*)d_in[3];
    const float* Whh = (const float*)d_in[4];
    const float* bih = (const float*)d_in[5];
    const float* bhh = (const float*)d_in[6];
    float* out = (float*)d_out;

    const int warps   = (BB + 2) / 3;                          // 683
    const int threads = 128;                                   // 4 warps / CTA
    const int blocks  = (warps * 32 + threads - 1) / threads;  // 171
    lstm_kernel<<<blocks, threads>>>(x, h0, c0, Wih, Whh, bih, bhh, out);
}